// round 10
// baseline (speedup 1.0000x reference)
#include <cuda_runtime.h>
#include <math.h>
#include <stdint.h>

#define Bsz 16384
#define Hd  1024
#define Cc  2
#define PPCc 24
#define Pp  48
#define EPSf 1e-4f

#define DIST_BLOCKS (Bsz / 64)          // 256
#define UALL_BLOCKS 512
#define COPY_BLOCKS 512                 // 32 rows each
#define COPY_BASE   (DIST_BLOCKS + UALL_BLOCKS)

#define XWORDS (64 * 36)
#define STAGE_WORDS ((64 + 48) * 36)
#define STAGE_BYTES (STAGE_WORDS * 4)
#define NSTAGE 4

// Output layout (concatenated reference tuple, all fp32):
//   pos [B,1] | shared [B,H] | logits [B,C] | distance [B,P]
#define POS_OFF    ((size_t)0)
#define SHARED_OFF ((size_t)Bsz)
#define LOGITS_OFF (SHARED_OFF + (size_t)Bsz * Hd)
#define DIST_OFF   (LOGITS_OFF + (size_t)Bsz * Cc)

// Scratch (no device allocs allowed; zeroed via cudaMemsetAsync graph nodes)
__device__ float g_simSum[Pp];
__device__ float g_uall[Pp * Hd];   // u_p = W^T proto_p (exact fp32)

__device__ __forceinline__ void cpa16(uint32_t dst, const void* src) {
    asm volatile("cp.async.cg.shared.global [%0], [%1], 16;"
                 :: "r"(dst), "l"(src));
}
__device__ __forceinline__ void cpa_commit() {
    asm volatile("cp.async.commit_group;" ::: "memory");
}
__device__ __forceinline__ void cpa_wait2() {
    asm volatile("cp.async.wait_group 2;" ::: "memory");
}

// ---------------------------------------------------------------------------
// K2 fused single launch, three roles:
//   [0, DIST):            tf32 distance GEMM (ldmatrix fragment loads)
//   [DIST, DIST+UALL):    u_all micro-blocks (exact fp32, split i/j/p)
//   [COPY_BASE, +COPY):   shared_user copy-out (ldcg keeps lines in L2)
// ---------------------------------------------------------------------------
__global__ __launch_bounds__(256, 3) void k2_fused(
    const float* __restrict__ x, const float* __restrict__ shr,
    const float* __restrict__ protos, const float* __restrict__ llw,
    const float* __restrict__ W, float* __restrict__ out) {
    __shared__ uint32_t pipe[NSTAGE][STAGE_WORDS];   // 64512 B

    const int tid = threadIdx.x;

    // ======================= role: shared copy-out =======================
    if (blockIdx.x >= COPY_BASE) {
        const int cb = blockIdx.x - COPY_BASE;            // 0..511
        const float4* s4 = (const float4*)shr;
        float4* d4 = (float4*)(out + SHARED_OFF);
        const size_t base = (size_t)cb * 8192 + tid;      // 8192 float4 / block
#pragma unroll 8
        for (int k = 0; k < 32; k++) {
            const float4 v = __ldcg(s4 + base + (size_t)k * 256);
            __stcs(d4 + base + (size_t)k * 256, v);
        }
        return;
    }

    // ======================= role: u_all =======================
    if (blockIdx.x >= DIST_BLOCKS) {
        float* psh = (float*)&pipe[0][0];      // 24*16 floats
        const int b  = blockIdx.x - DIST_BLOCKS;
        const int j0 = (b & 3) * 256;
        const int i0 = ((b >> 2) & 63) * 16;
        const int ph = b >> 8;                 // proto half: 0 or 1
        if (tid < 24 * 16) {
            const int p = tid >> 4, i = tid & 15;
            psh[tid] = protos[(size_t)(ph * 24 + p) * Hd + i0 + i];
        }
        __syncthreads();
        const int j = j0 + tid;
        float acc[24];
#pragma unroll
        for (int p = 0; p < 24; p++) acc[p] = 0.f;
        const float* Wp = W + (size_t)i0 * Hd + j;
#pragma unroll
        for (int i = 0; i < 16; i += 8) {
            float w[8];
#pragma unroll
            for (int q = 0; q < 8; q++) w[q] = __ldcs(Wp + (size_t)(i + q) * Hd);
#pragma unroll
            for (int p = 0; p < 24; p++) {
                float a = acc[p];
#pragma unroll
                for (int q = 0; q < 8; q++) a = fmaf(w[q], psh[p * 16 + i + q], a);
                acc[p] = a;
            }
        }
#pragma unroll
        for (int p = 0; p < 24; p++)
            atomicAdd(&g_uall[(ph * 24 + p) * Hd + j], acc[p]);
        return;
    }

    // ======================= role: distance GEMM =======================
    const int lane = tid & 31, warp = tid >> 5;
    const int row0 = blockIdx.x * 64;
    const int g  = lane >> 2;
    const int t4 = lane & 3;

    const int xrow = tid >> 3;                 // 0..31
    const int xk4  = (tid & 7) << 2;
    const float* xbase  = x + (size_t)(row0 + xrow) * Hd + xk4;
    const float* pbase0 = protos + (size_t)xrow * Hd + xk4;
    const float* pbase1 = protos + (size_t)(xrow + 32) * Hd + xk4;
    const bool   phas1  = (tid < 128);         // proto rows 32..47

    const uint32_t smem0 = (uint32_t)__cvta_generic_to_shared(&pipe[0][0]);
    const uint32_t dx0 = (xrow * 36 + xk4) * 4;
    const uint32_t dx1 = ((xrow + 32) * 36 + xk4) * 4;
    const uint32_t dp0 = (XWORDS + xrow * 36 + xk4) * 4;
    const uint32_t dp1 = (XWORDS + (xrow + 32) * 36 + xk4) * 4;

#define ISSUE_STAGE(S, BUF)                                              \
    do {                                                                 \
        const int _ko = (S) * 32;                                        \
        const uint32_t _b = smem0 + (BUF) * STAGE_BYTES;                 \
        cpa16(_b + dx0, xbase + _ko);                                    \
        cpa16(_b + dx1, xbase + (size_t)32 * Hd + _ko);                  \
        cpa16(_b + dp0, pbase0 + _ko);                                   \
        if (phas1) cpa16(_b + dp1, pbase1 + _ko);                        \
    } while (0)

    ISSUE_STAGE(0, 0); cpa_commit();
    ISSUE_STAGE(1, 1); cpa_commit();
    ISSUE_STAGE(2, 2); cpa_commit();

    float acc[3][4];
#pragma unroll
    for (int n = 0; n < 3; n++)
#pragma unroll
        for (int q = 0; q < 4; q++) acc[n][q] = 0.f;
    float sqA = 0.f, sqB = 0.f;
    float pq[3] = {0.f, 0.f, 0.f};

    const int Rg    = (warp & 3) * 16 + g;     // A rows Rg, Rg+8
    const int nhalf = warp >> 2;
    const bool doX2 = (nhalf == 0);
    const bool doP2 = ((warp & 3) == 0);

    // ldmatrix per-lane base addresses (stage-0 buffer)
    const int rbase = (warp & 3) * 16;
    const uint32_t rowA  = rbase + (lane & 7) + ((lane >> 3) & 1) * 8;
    const uint32_t wordA = (lane >> 4) * 4;
    const uint32_t aAddr0 = smem0 + (rowA * 36 + wordA) * 4;
    const uint32_t rowB4  = (nhalf * 3 + (lane >> 4)) * 8 + (lane & 7);
    const uint32_t wordB4 = ((lane >> 3) & 1) * 4;
    const uint32_t b4Addr0 = smem0 + (XWORDS + rowB4 * 36 + wordB4) * 4;
    const uint32_t rowB2  = (nhalf * 3 + 2) * 8 + (lane & 7);
    const uint32_t wordB2 = ((lane >> 3) & 1) * 4;
    const uint32_t b2Addr0 = smem0 + (XWORDS + rowB2 * 36 + wordB2) * 4;

    for (int s = 0; s < 32; s++) {
        cpa_wait2();
        __syncthreads();
        if (s + 3 < 32) { const int b3 = (s + 3) & 3; ISSUE_STAGE(s + 3, b3); }
        cpa_commit();

        const uint32_t stof = (uint32_t)(s & 3) * STAGE_BYTES;
        const uint32_t aA  = aAddr0  + stof;
        const uint32_t aB4 = b4Addr0 + stof;
        const uint32_t aB2 = b2Addr0 + stof;
#pragma unroll
        for (int kc = 0; kc < 32; kc += 8) {
            uint32_t a0, a1, a2, a3;
            asm volatile(
                "ldmatrix.sync.aligned.m8n8.x4.shared.b16 {%0,%1,%2,%3}, [%4];"
                : "=r"(a0), "=r"(a1), "=r"(a2), "=r"(a3)
                : "r"(aA + kc * 4));
            uint32_t b00, b01, b10, b11;
            asm volatile(
                "ldmatrix.sync.aligned.m8n8.x4.shared.b16 {%0,%1,%2,%3}, [%4];"
                : "=r"(b00), "=r"(b01), "=r"(b10), "=r"(b11)
                : "r"(aB4 + kc * 4));
            uint32_t b20, b21;
            asm volatile(
                "ldmatrix.sync.aligned.m8n8.x2.shared.b16 {%0,%1}, [%2];"
                : "=r"(b20), "=r"(b21)
                : "r"(aB2 + kc * 4));

            if (doX2) {
                const float f0 = __uint_as_float(a0), f1 = __uint_as_float(a1);
                const float f2 = __uint_as_float(a2), f3 = __uint_as_float(a3);
                sqA = fmaf(f0, f0, sqA); sqA = fmaf(f2, f2, sqA);
                sqB = fmaf(f1, f1, sqB); sqB = fmaf(f3, f3, sqB);
            }
            if (doP2) {
                const float h0 = __uint_as_float(b00), h1 = __uint_as_float(b01);
                const float h2 = __uint_as_float(b10), h3 = __uint_as_float(b11);
                const float h4 = __uint_as_float(b20), h5 = __uint_as_float(b21);
                pq[0] = fmaf(h0, h0, pq[0]); pq[0] = fmaf(h1, h1, pq[0]);
                pq[1] = fmaf(h2, h2, pq[1]); pq[1] = fmaf(h3, h3, pq[1]);
                pq[2] = fmaf(h4, h4, pq[2]); pq[2] = fmaf(h5, h5, pq[2]);
            }
            asm volatile(
                "mma.sync.aligned.m16n8k8.row.col.f32.tf32.tf32.f32 "
                "{%0,%1,%2,%3}, {%4,%5,%6,%7}, {%8,%9}, {%0,%1,%2,%3};"
                : "+f"(acc[0][0]), "+f"(acc[0][1]), "+f"(acc[0][2]), "+f"(acc[0][3])
                : "r"(a0), "r"(a1), "r"(a2), "r"(a3), "r"(b00), "r"(b01));
            asm volatile(
                "mma.sync.aligned.m16n8k8.row.col.f32.tf32.tf32.f32 "
                "{%0,%1,%2,%3}, {%4,%5,%6,%7}, {%8,%9}, {%0,%1,%2,%3};"
                : "+f"(acc[1][0]), "+f"(acc[1][1]), "+f"(acc[1][2]), "+f"(acc[1][3])
                : "r"(a0), "r"(a1), "r"(a2), "r"(a3), "r"(b10), "r"(b11));
            asm volatile(
                "mma.sync.aligned.m16n8k8.row.col.f32.tf32.tf32.f32 "
                "{%0,%1,%2,%3}, {%4,%5,%6,%7}, {%8,%9}, {%0,%1,%2,%3};"
                : "+f"(acc[2][0]), "+f"(acc[2][1]), "+f"(acc[2][2]), "+f"(acc[2][3])
                : "r"(a0), "r"(a1), "r"(a2), "r"(a3), "r"(b20), "r"(b21));
        }
    }
    __syncthreads();   // all mma done; safe to alias pipe as epilogue scratch

    // aliased epilogue scratch in pipe[0]
    float* ext     = (float*)&pipe[0][0];
    float* x2s     = ext;          // 64
    float* p2s     = ext + 64;     // 48
    float* logit_s = ext + 112;    // 128
    float* simPart = ext + 240;    // 48
    float* wks     = ext + 288;    // 96
    for (int i = tid; i < 384; i += 256)
        ext[i] = (i < 288) ? 0.f : llw[i - 288];
    __syncthreads();

    // quad-reduce squared norms (lanes t4=0..3 share a row)
    sqA += __shfl_xor_sync(0xffffffffu, sqA, 1);
    sqA += __shfl_xor_sync(0xffffffffu, sqA, 2);
    sqB += __shfl_xor_sync(0xffffffffu, sqB, 1);
    sqB += __shfl_xor_sync(0xffffffffu, sqB, 2);
    if (doX2 && t4 == 0) {
        atomicAdd(&x2s[Rg],     sqA);
        atomicAdd(&x2s[Rg + 8], sqB);
    }
#pragma unroll
    for (int nt = 0; nt < 3; nt++) {
        pq[nt] += __shfl_xor_sync(0xffffffffu, pq[nt], 1);
        pq[nt] += __shfl_xor_sync(0xffffffffu, pq[nt], 2);
    }
    if (doP2 && t4 == 0) {
#pragma unroll
        for (int nt = 0; nt < 3; nt++)
            atomicAdd(&p2s[(nhalf * 3 + nt) * 8 + g], pq[nt]);
    }
    __syncthreads();

    const int ra = Rg, rb = Rg + 8;
    const float x2a = x2s[ra], x2b = x2s[rb];
    float lgA0 = 0.f, lgA1 = 0.f, lgB0 = 0.f, lgB1 = 0.f;
    float* dd = out + DIST_OFF + (size_t)row0 * 48;
#pragma unroll
    for (int nt = 0; nt < 3; nt++) {
        const int c0 = (nhalf * 3 + nt) * 8 + t4 * 2, c1 = c0 + 1;
        const float dA0 = fmaf(-2.f, acc[nt][0], x2a + p2s[c0]);
        const float dA1 = fmaf(-2.f, acc[nt][1], x2a + p2s[c1]);
        const float dB0 = fmaf(-2.f, acc[nt][2], x2b + p2s[c0]);
        const float dB1 = fmaf(-2.f, acc[nt][3], x2b + p2s[c1]);
        __stcs((float2*)(dd + (size_t)ra * 48 + c0), make_float2(dA0, dA1));
        __stcs((float2*)(dd + (size_t)rb * 48 + c0), make_float2(dB0, dB1));
        const float sA0 = logf((dA0 + 1.f) / (dA0 + EPSf));
        const float sA1 = logf((dA1 + 1.f) / (dA1 + EPSf));
        const float sB0 = logf((dB0 + 1.f) / (dB0 + EPSf));
        const float sB1 = logf((dB1 + 1.f) / (dB1 + EPSf));
        lgA0 = fmaf(sA0, wks[c0], lgA0); lgA0 = fmaf(sA1, wks[c1], lgA0);
        lgA1 = fmaf(sA0, wks[48 + c0], lgA1); lgA1 = fmaf(sA1, wks[48 + c1], lgA1);
        lgB0 = fmaf(sB0, wks[c0], lgB0); lgB0 = fmaf(sB1, wks[c1], lgB0);
        lgB1 = fmaf(sB0, wks[48 + c0], lgB1); lgB1 = fmaf(sB1, wks[48 + c1], lgB1);
        atomicAdd(&simPart[c0], sA0 + sB0);
        atomicAdd(&simPart[c1], sA1 + sB1);
    }
    atomicAdd(&logit_s[ra * 2 + 0], lgA0);
    atomicAdd(&logit_s[ra * 2 + 1], lgA1);
    atomicAdd(&logit_s[rb * 2 + 0], lgB0);
    atomicAdd(&logit_s[rb * 2 + 1], lgB1);
    __syncthreads();

    if (tid < 128) out[LOGITS_OFF + (size_t)row0 * 2 + tid] = logit_s[tid];
    if (tid < 48)  atomicAdd(&g_simSum[tid], simPart[tid]);
#undef ISSUE_STAGE
}

// ---------------------------------------------------------------------------
// K4: argmax -> u[jstar] -> pos dot only (shared re-read hits L2 from the
// copy role's __ldcg traffic in the previous launch).
// ---------------------------------------------------------------------------
__global__ __launch_bounds__(512) void k4_dot(
    const float* __restrict__ shr, const float* __restrict__ bb,
    const int* __restrict__ flag, float* __restrict__ out) {
    __shared__ float us[Hd];
    __shared__ int   js_s;
    const int tid = threadIdx.x;

    if (tid < 32) {
        const int idx = (flag[0] != 0) ? 1 : 0;
        float v = (tid < PPCc) ? g_simSum[idx * PPCc + tid] : -INFINITY;
        int bj = tid;
        for (int o = 16; o; o >>= 1) {
            const float ov = __shfl_xor_sync(0xffffffffu, v, o);
            const int   oj = __shfl_xor_sync(0xffffffffu, bj, o);
            if (ov > v || (ov == v && oj < bj)) { v = ov; bj = oj; }
        }
        if (tid == 0) js_s = idx * PPCc + bj;
    }
    __syncthreads();
    const int js = js_s;
    for (int i = tid; i < Hd; i += 512) us[i] = g_uall[js * Hd + i];
    __syncthreads();

    const int warp = tid >> 5, lane = tid & 31;
    const int r = blockIdx.x * 16 + warp;
    const float4* src = (const float4*)(shr + (size_t)r * Hd);
    const float4* uf  = (const float4*)us;
    float a0 = 0.f, a1 = 0.f, a2 = 0.f, a3 = 0.f;
#pragma unroll
    for (int t = lane; t < Hd / 4; t += 32) {
        const float4 v  = __ldcg(src + t);
        const float4 u4 = uf[t];
        a0 = fmaf(v.x, u4.x, a0);
        a1 = fmaf(v.y, u4.y, a1);
        a2 = fmaf(v.z, u4.z, a2);
        a3 = fmaf(v.w, u4.w, a3);
    }
    float acc = (a0 + a1) + (a2 + a3);
    for (int o = 16; o; o >>= 1) acc += __shfl_xor_sync(0xffffffffu, acc, o);
    if (lane == 0) out[POS_OFF + r] = acc + __ldg(bb);
}

// ---------------------------------------------------------------------------
extern "C" void kernel_launch(void* const* d_in, const int* in_sizes, int n_in,
                              void* d_out, int out_size) {
    const float* x      = (const float*)d_in[0];  // specific_user [B,H]
    const float* shr    = (const float*)d_in[1];  // shared_user   [B,H]
    const float* protos = (const float*)d_in[2];  // [P,H]
    const float* llw    = (const float*)d_in[3];  // [C,P]
    const float* W      = (const float*)d_in[4];  // [1,H,H]
    const float* bb     = (const float*)d_in[5];  // [1]
    const int*   flag   = (const int*)d_in[6];    // scalar
    float* out = (float*)d_out;

    void* uall_ptr = nullptr;
    void* ssum_ptr = nullptr;
    cudaGetSymbolAddress(&uall_ptr, g_uall);
    cudaGetSymbolAddress(&ssum_ptr, g_simSum);
    cudaMemsetAsync(uall_ptr, 0, (size_t)Pp * Hd * sizeof(float));
    cudaMemsetAsync(ssum_ptr, 0, (size_t)Pp * sizeof(float));

    k2_fused<<<DIST_BLOCKS + UALL_BLOCKS + COPY_BLOCKS, 256>>>(
        x, shr, protos, llw, W, out);
    k4_dot  <<<Bsz / 16, 512>>>(shr, bb, flag, out);
}

// round 11
// speedup vs baseline: 1.0221x; 1.0221x over previous
#include <cuda_runtime.h>
#include <math.h>
#include <stdint.h>

#define Bsz 16384
#define Hd  1024
#define Cc  2
#define PPCc 24
#define Pp  48
#define EPSf 1e-4f

#define DIST_BLOCKS (Bsz / 64)          // 256
#define UALL_BLOCKS 512

#define XWORDS (64 * 36)
#define STAGE_WORDS ((64 + 48) * 36)
#define STAGE_BYTES (STAGE_WORDS * 4)
#define NSTAGE 3

// Output layout (concatenated reference tuple, all fp32):
//   pos [B,1] | shared [B,H] | logits [B,C] | distance [B,P]
#define POS_OFF    ((size_t)0)
#define SHARED_OFF ((size_t)Bsz)
#define LOGITS_OFF (SHARED_OFF + (size_t)Bsz * Hd)
#define DIST_OFF   (LOGITS_OFF + (size_t)Bsz * Cc)

// Scratch (no device allocs allowed; zeroed via cudaMemsetAsync graph nodes)
__device__ float g_simSum[Pp];
__device__ float g_uall[Pp * Hd];   // u_p = W^T proto_p (exact fp32)

__device__ __forceinline__ void cpa16(uint32_t dst, const void* src) {
    asm volatile("cp.async.cg.shared.global [%0], [%1], 16;"
                 :: "r"(dst), "l"(src));
}
__device__ __forceinline__ void cpa_commit() {
    asm volatile("cp.async.commit_group;" ::: "memory");
}
__device__ __forceinline__ void cpa_wait1() {
    asm volatile("cp.async.wait_group 1;" ::: "memory");
}

// ---------------------------------------------------------------------------
// K2 fused single launch:
//   blocks [0, DIST_BLOCKS):  tf32 distance GEMM (3-stage cp.async pipeline)
//   blocks [DIST_BLOCKS, ..): u_all micro-blocks (exact fp32, split i/j/p)
// ---------------------------------------------------------------------------
__global__ __launch_bounds__(256, 3) void k2_fused(
    const float* __restrict__ x, const float* __restrict__ protos,
    const float* __restrict__ llw, const float* __restrict__ W,
    float* __restrict__ out) {
    __shared__ uint32_t pipe[NSTAGE][STAGE_WORDS];   // 48384 B

    const int tid = threadIdx.x;

    // ======================= role: u_all =======================
    if (blockIdx.x >= DIST_BLOCKS) {
        float* psh = (float*)&pipe[0][0];      // 24*16 floats
        const int b  = blockIdx.x - DIST_BLOCKS;
        const int j0 = (b & 3) * 256;
        const int i0 = ((b >> 2) & 63) * 16;
        const int ph = b >> 8;                 // proto half: 0 or 1
        if (tid < 24 * 16) {
            const int p = tid >> 4, i = tid & 15;
            psh[tid] = protos[(size_t)(ph * 24 + p) * Hd + i0 + i];
        }
        __syncthreads();
        const int j = j0 + tid;
        float acc[24];
#pragma unroll
        for (int p = 0; p < 24; p++) acc[p] = 0.f;
        const float* Wp = W + (size_t)i0 * Hd + j;
#pragma unroll
        for (int i = 0; i < 16; i += 8) {
            float w[8];
#pragma unroll
            for (int q = 0; q < 8; q++) w[q] = __ldcs(Wp + (size_t)(i + q) * Hd);
#pragma unroll
            for (int p = 0; p < 24; p++) {
                float a = acc[p];
#pragma unroll
                for (int q = 0; q < 8; q++) a = fmaf(w[q], psh[p * 16 + i + q], a);
                acc[p] = a;
            }
        }
#pragma unroll
        for (int p = 0; p < 24; p++)
            atomicAdd(&g_uall[(ph * 24 + p) * Hd + j], acc[p]);
        return;
    }

    // ======================= role: distance GEMM =======================
    const int lane = tid & 31, warp = tid >> 5;
    const int row0 = blockIdx.x * 64;
    const int g  = lane >> 2;
    const int t4 = lane & 3;

    const int xrow = tid >> 3;                 // 0..31
    const int xk4  = (tid & 7) << 2;
    const float* xbase  = x + (size_t)(row0 + xrow) * Hd + xk4;
    const float* pbase0 = protos + (size_t)xrow * Hd + xk4;
    const float* pbase1 = protos + (size_t)(xrow + 32) * Hd + xk4;
    const bool   phas1  = (tid < 128);         // proto rows 32..47

    const uint32_t smem0 = (uint32_t)__cvta_generic_to_shared(&pipe[0][0]);
    const uint32_t dx0 = (xrow * 36 + xk4) * 4;
    const uint32_t dx1 = ((xrow + 32) * 36 + xk4) * 4;
    const uint32_t dp0 = (XWORDS + xrow * 36 + xk4) * 4;
    const uint32_t dp1 = (XWORDS + (xrow + 32) * 36 + xk4) * 4;

#define ISSUE_STAGE(S, BUF)                                              \
    do {                                                                 \
        const int _ko = (S) * 32;                                        \
        const uint32_t _b = smem0 + (BUF) * STAGE_BYTES;                 \
        cpa16(_b + dx0, xbase + _ko);                                    \
        cpa16(_b + dx1, xbase + (size_t)32 * Hd + _ko);                  \
        cpa16(_b + dp0, pbase0 + _ko);                                   \
        if (phas1) cpa16(_b + dp1, pbase1 + _ko);                        \
    } while (0)

    ISSUE_STAGE(0, 0); cpa_commit();
    ISSUE_STAGE(1, 1); cpa_commit();

    float acc[3][4];
#pragma unroll
    for (int n = 0; n < 3; n++)
#pragma unroll
        for (int q = 0; q < 4; q++) acc[n][q] = 0.f;
    float sqA = 0.f, sqB = 0.f;
    float pq[3] = {0.f, 0.f, 0.f};

    const int Rg    = (warp & 3) * 16 + g;     // A rows Rg, Rg+8
    const int nhalf = warp >> 2;
    const bool doX2 = (nhalf == 0);
    const bool doP2 = ((warp & 3) == 0);

    for (int s = 0; s < 32; s++) {
        cpa_wait1();
        __syncthreads();
        if (s + 2 < 32) { const int b2 = (s + 2) % 3; ISSUE_STAGE(s + 2, b2); }
        cpa_commit();

        const uint32_t* xb = &pipe[s % 3][0];
        const uint32_t* pb = xb + XWORDS;
#pragma unroll
        for (int kc = 0; kc < 32; kc += 8) {
            const uint32_t a0 = xb[(Rg    ) * 36 + kc + t4];
            const uint32_t a1 = xb[(Rg + 8) * 36 + kc + t4];
            const uint32_t a2 = xb[(Rg    ) * 36 + kc + t4 + 4];
            const uint32_t a3 = xb[(Rg + 8) * 36 + kc + t4 + 4];
            if (doX2) {
                const float f0 = __uint_as_float(a0), f1 = __uint_as_float(a1);
                const float f2 = __uint_as_float(a2), f3 = __uint_as_float(a3);
                sqA = fmaf(f0, f0, sqA); sqA = fmaf(f2, f2, sqA);
                sqB = fmaf(f1, f1, sqB); sqB = fmaf(f3, f3, sqB);
            }
#pragma unroll
            for (int nt = 0; nt < 3; nt++) {
                const int prow = (nhalf * 3 + nt) * 8 + g;
                const uint32_t b0 = pb[prow * 36 + kc + t4];
                const uint32_t b1 = pb[prow * 36 + kc + t4 + 4];
                if (doP2) {
                    const float h0 = __uint_as_float(b0), h1 = __uint_as_float(b1);
                    pq[nt] = fmaf(h0, h0, pq[nt]);
                    pq[nt] = fmaf(h1, h1, pq[nt]);
                }
                asm volatile(
                    "mma.sync.aligned.m16n8k8.row.col.f32.tf32.tf32.f32 "
                    "{%0,%1,%2,%3}, {%4,%5,%6,%7}, {%8,%9}, {%0,%1,%2,%3};"
                    : "+f"(acc[nt][0]), "+f"(acc[nt][1]),
                      "+f"(acc[nt][2]), "+f"(acc[nt][3])
                    : "r"(a0), "r"(a1), "r"(a2), "r"(a3), "r"(b0), "r"(b1));
            }
        }
    }
    __syncthreads();   // all mma done; safe to alias pipe as epilogue scratch

    // aliased epilogue scratch in pipe[0]
    float* ext     = (float*)&pipe[0][0];
    float* x2s     = ext;          // 64
    float* p2s     = ext + 64;     // 48
    float* logit_s = ext + 112;    // 128
    float* simPart = ext + 240;    // 48
    float* wks     = ext + 288;    // 96
    for (int i = tid; i < 384; i += 256)
        ext[i] = (i < 288) ? 0.f : llw[i - 288];
    __syncthreads();

    // quad-reduce squared norms (lanes t4=0..3 share a row)
    sqA += __shfl_xor_sync(0xffffffffu, sqA, 1);
    sqA += __shfl_xor_sync(0xffffffffu, sqA, 2);
    sqB += __shfl_xor_sync(0xffffffffu, sqB, 1);
    sqB += __shfl_xor_sync(0xffffffffu, sqB, 2);
    if (doX2 && t4 == 0) {
        atomicAdd(&x2s[Rg],     sqA);
        atomicAdd(&x2s[Rg + 8], sqB);
    }
#pragma unroll
    for (int nt = 0; nt < 3; nt++) {
        pq[nt] += __shfl_xor_sync(0xffffffffu, pq[nt], 1);
        pq[nt] += __shfl_xor_sync(0xffffffffu, pq[nt], 2);
    }
    if (doP2 && t4 == 0) {
#pragma unroll
        for (int nt = 0; nt < 3; nt++)
            atomicAdd(&p2s[(nhalf * 3 + nt) * 8 + g], pq[nt]);
    }
    __syncthreads();

    const int ra = Rg, rb = Rg + 8;
    const float x2a = x2s[ra], x2b = x2s[rb];
    float lgA0 = 0.f, lgA1 = 0.f, lgB0 = 0.f, lgB1 = 0.f;
    float* dd = out + DIST_OFF + (size_t)row0 * 48;
#pragma unroll
    for (int nt = 0; nt < 3; nt++) {
        const int c0 = (nhalf * 3 + nt) * 8 + t4 * 2, c1 = c0 + 1;
        const float dA0 = fmaf(-2.f, acc[nt][0], x2a + p2s[c0]);
        const float dA1 = fmaf(-2.f, acc[nt][1], x2a + p2s[c1]);
        const float dB0 = fmaf(-2.f, acc[nt][2], x2b + p2s[c0]);
        const float dB1 = fmaf(-2.f, acc[nt][3], x2b + p2s[c1]);
        __stcs((float2*)(dd + (size_t)ra * 48 + c0), make_float2(dA0, dA1));
        __stcs((float2*)(dd + (size_t)rb * 48 + c0), make_float2(dB0, dB1));
        const float sA0 = __logf(__fdividef(dA0 + 1.f, dA0 + EPSf));
        const float sA1 = __logf(__fdividef(dA1 + 1.f, dA1 + EPSf));
        const float sB0 = __logf(__fdividef(dB0 + 1.f, dB0 + EPSf));
        const float sB1 = __logf(__fdividef(dB1 + 1.f, dB1 + EPSf));
        lgA0 = fmaf(sA0, wks[c0], lgA0); lgA0 = fmaf(sA1, wks[c1], lgA0);
        lgA1 = fmaf(sA0, wks[48 + c0], lgA1); lgA1 = fmaf(sA1, wks[48 + c1], lgA1);
        lgB0 = fmaf(sB0, wks[c0], lgB0); lgB0 = fmaf(sB1, wks[c1], lgB0);
        lgB1 = fmaf(sB0, wks[48 + c0], lgB1); lgB1 = fmaf(sB1, wks[48 + c1], lgB1);
        atomicAdd(&simPart[c0], sA0 + sB0);
        atomicAdd(&simPart[c1], sA1 + sB1);
    }
    atomicAdd(&logit_s[ra * 2 + 0], lgA0);
    atomicAdd(&logit_s[ra * 2 + 1], lgA1);
    atomicAdd(&logit_s[rb * 2 + 0], lgB0);
    atomicAdd(&logit_s[rb * 2 + 1], lgB1);
    __syncthreads();

    if (tid < 128) out[LOGITS_OFF + (size_t)row0 * 2 + tid] = logit_s[tid];
    if (tid < 48)  atomicAdd(&g_simSum[tid], simPart[tid]);
#undef ISSUE_STAGE
}

// ---------------------------------------------------------------------------
// K3: in-block argmax -> u[jstar] to smem -> fused shared copy-out + pos dot.
// ---------------------------------------------------------------------------
__global__ __launch_bounds__(512) void k3_pos(
    const float* __restrict__ shr, const float* __restrict__ bb,
    const int* __restrict__ flag, float* __restrict__ out) {
    __shared__ float us[Hd];
    __shared__ int   js_s;
    const int tid = threadIdx.x;

    if (tid < 32) {
        const int idx = (flag[0] != 0) ? 1 : 0;
        float v = (tid < PPCc) ? g_simSum[idx * PPCc + tid] : -INFINITY;
        int bj = tid;
        for (int o = 16; o; o >>= 1) {
            const float ov = __shfl_xor_sync(0xffffffffu, v, o);
            const int   oj = __shfl_xor_sync(0xffffffffu, bj, o);
            if (ov > v || (ov == v && oj < bj)) { v = ov; bj = oj; }
        }
        if (tid == 0) js_s = idx * PPCc + bj;
    }
    __syncthreads();
    const int js = js_s;
    for (int i = tid; i < Hd; i += 512) us[i] = g_uall[js * Hd + i];
    __syncthreads();

    const int warp = tid >> 5, lane = tid & 31;
    const int r = blockIdx.x * 16 + warp;
    const float4* src = (const float4*)(shr + (size_t)r * Hd);
    float4*       dst = (float4*)(out + SHARED_OFF + (size_t)r * Hd);
    const float4* uf  = (const float4*)us;
    float a0 = 0.f, a1 = 0.f, a2 = 0.f, a3 = 0.f;
#pragma unroll
    for (int t = lane; t < Hd / 4; t += 32) {
        const float4 v = __ldcs(src + t);
        __stcs(dst + t, v);
        const float4 u4 = uf[t];
        a0 = fmaf(v.x, u4.x, a0);
        a1 = fmaf(v.y, u4.y, a1);
        a2 = fmaf(v.z, u4.z, a2);
        a3 = fmaf(v.w, u4.w, a3);
    }
    float acc = (a0 + a1) + (a2 + a3);
    for (int o = 16; o; o >>= 1) acc += __shfl_xor_sync(0xffffffffu, acc, o);
    if (lane == 0) out[POS_OFF + r] = acc + __ldg(bb);
}

// ---------------------------------------------------------------------------
// Dummy no-op kernels: pad the per-replay kernel-launch count to 5 so that
// ncu's "-s 5 -c 1" capture (launch #6) lands on k2_fused instead of the
// trailing kernel. ~1us total cost; removed once k2's profile is understood.
// ---------------------------------------------------------------------------
__global__ void k_nop1() {}
__global__ void k_nop2() {}
__global__ void k_nop3() {}

// ---------------------------------------------------------------------------
extern "C" void kernel_launch(void* const* d_in, const int* in_sizes, int n_in,
                              void* d_out, int out_size) {
    const float* x      = (const float*)d_in[0];  // specific_user [B,H]
    const float* shr    = (const float*)d_in[1];  // shared_user   [B,H]
    const float* protos = (const float*)d_in[2];  // [P,H]
    const float* llw    = (const float*)d_in[3];  // [C,P]
    const float* W      = (const float*)d_in[4];  // [1,H,H]
    const float* bb     = (const float*)d_in[5];  // [1]
    const int*   flag   = (const int*)d_in[6];    // scalar
    float* out = (float*)d_out;

    void* uall_ptr = nullptr;
    void* ssum_ptr = nullptr;
    cudaGetSymbolAddress(&uall_ptr, g_uall);
    cudaGetSymbolAddress(&ssum_ptr, g_simSum);
    cudaMemsetAsync(uall_ptr, 0, (size_t)Pp * Hd * sizeof(float));
    cudaMemsetAsync(ssum_ptr, 0, (size_t)Pp * sizeof(float));

    k2_fused<<<DIST_BLOCKS + UALL_BLOCKS, 256>>>(x, protos, llw, W, out);
    k3_pos  <<<Bsz / 16, 512>>>(shr, bb, flag, out);
    k_nop1  <<<1, 32>>>();
    k_nop2  <<<1, 32>>>();
    k_nop3  <<<1, 32>>>();
}

// round 12
// speedup vs baseline: 1.2185x; 1.1921x over previous
#include <cuda_runtime.h>
#include <math.h>
#include <stdint.h>

#define Bsz 16384
#define Hd  1024
#define Cc  2
#define PPCc 24
#define Pp  48
#define EPSf 1e-4f

#define DIST_BLOCKS (Bsz / 64)          // 256
#define UALL_BLOCKS 128                 // 4 j-chunks x 16 i-splits x 2 halves

#define XWORDS (64 * 36)
#define STAGE_WORDS ((64 + 48) * 36)
#define STAGE_BYTES (STAGE_WORDS * 4)
#define NSTAGE 3

// Output layout (concatenated reference tuple, all fp32):
//   pos [B,1] | shared [B,H] | logits [B,C] | distance [B,P]
#define POS_OFF    ((size_t)0)
#define SHARED_OFF ((size_t)Bsz)
#define LOGITS_OFF (SHARED_OFF + (size_t)Bsz * Hd)
#define DIST_OFF   (LOGITS_OFF + (size_t)Bsz * Cc)

// Single scratch symbol -> ONE memset node per replay.
//   [0, Pp*Hd)        : u_all  (u_p = W^T proto_p, exact fp32)
//   [Pp*Hd, Pp*Hd+Pp) : simSum
__device__ float g_scratch[Pp * Hd + Pp];
#define G_UALL   (g_scratch)
#define G_SIMSUM (g_scratch + Pp * Hd)

__device__ __forceinline__ void cpa16(uint32_t dst, const void* src) {
    asm volatile("cp.async.cg.shared.global [%0], [%1], 16;"
                 :: "r"(dst), "l"(src));
}
__device__ __forceinline__ void cpa_commit() {
    asm volatile("cp.async.commit_group;" ::: "memory");
}
__device__ __forceinline__ void cpa_wait1() {
    asm volatile("cp.async.wait_group 1;" ::: "memory");
}

// ---------------------------------------------------------------------------
// K2 fused single launch:
//   blocks [0, DIST_BLOCKS):  tf32 distance GEMM (3-stage cp.async pipeline)
//   blocks [DIST_BLOCKS, ..): u_all blocks (exact fp32; 64-deep i-chunks,
//                             4x fewer global atomics than the 512-block form)
// ---------------------------------------------------------------------------
__global__ __launch_bounds__(256, 3) void k2_fused(
    const float* __restrict__ x, const float* __restrict__ protos,
    const float* __restrict__ llw, const float* __restrict__ W,
    float* __restrict__ out) {
    __shared__ uint32_t pipe[NSTAGE][STAGE_WORDS];   // 48384 B

    const int tid = threadIdx.x;

    // ======================= role: u_all =======================
    if (blockIdx.x >= DIST_BLOCKS) {
        float* psh = (float*)&pipe[0][0];      // 24*64 floats = 6 KB
        const int b  = blockIdx.x - DIST_BLOCKS;
        const int j0 = (b & 3) * 256;
        const int i0 = ((b >> 2) & 15) * 64;
        const int ph = b >> 6;                 // proto half: 0 or 1
        for (int idx = tid; idx < 24 * 64; idx += 256) {
            const int p = idx >> 6, i = idx & 63;
            psh[idx] = protos[(size_t)(ph * 24 + p) * Hd + i0 + i];
        }
        __syncthreads();
        const int j = j0 + tid;
        float acc[24];
#pragma unroll
        for (int p = 0; p < 24; p++) acc[p] = 0.f;
        const float* Wp = W + (size_t)i0 * Hd + j;
#pragma unroll 2
        for (int i = 0; i < 64; i += 8) {
            float w[8];
#pragma unroll
            for (int q = 0; q < 8; q++) w[q] = __ldcs(Wp + (size_t)(i + q) * Hd);
#pragma unroll
            for (int p = 0; p < 24; p++) {
                float a = acc[p];
#pragma unroll
                for (int q = 0; q < 8; q++) a = fmaf(w[q], psh[p * 64 + i + q], a);
                acc[p] = a;
            }
        }
#pragma unroll
        for (int p = 0; p < 24; p++)
            atomicAdd(&G_UALL[(ph * 24 + p) * Hd + j], acc[p]);
        return;
    }

    // ======================= role: distance GEMM =======================
    const int lane = tid & 31, warp = tid >> 5;
    const int row0 = blockIdx.x * 64;
    const int g  = lane >> 2;
    const int t4 = lane & 3;

    const int xrow = tid >> 3;                 // 0..31
    const int xk4  = (tid & 7) << 2;
    const float* xbase  = x + (size_t)(row0 + xrow) * Hd + xk4;
    const float* pbase0 = protos + (size_t)xrow * Hd + xk4;
    const float* pbase1 = protos + (size_t)(xrow + 32) * Hd + xk4;
    const bool   phas1  = (tid < 128);         // proto rows 32..47

    const uint32_t smem0 = (uint32_t)__cvta_generic_to_shared(&pipe[0][0]);
    const uint32_t dx0 = (xrow * 36 + xk4) * 4;
    const uint32_t dx1 = ((xrow + 32) * 36 + xk4) * 4;
    const uint32_t dp0 = (XWORDS + xrow * 36 + xk4) * 4;
    const uint32_t dp1 = (XWORDS + (xrow + 32) * 36 + xk4) * 4;

#define ISSUE_STAGE(S, BUF)                                              \
    do {                                                                 \
        const int _ko = (S) * 32;                                        \
        const uint32_t _b = smem0 + (BUF) * STAGE_BYTES;                 \
        cpa16(_b + dx0, xbase + _ko);                                    \
        cpa16(_b + dx1, xbase + (size_t)32 * Hd + _ko);                  \
        cpa16(_b + dp0, pbase0 + _ko);                                   \
        if (phas1) cpa16(_b + dp1, pbase1 + _ko);                        \
    } while (0)

    ISSUE_STAGE(0, 0); cpa_commit();
    ISSUE_STAGE(1, 1); cpa_commit();

    float acc[3][4];
#pragma unroll
    for (int n = 0; n < 3; n++)
#pragma unroll
        for (int q = 0; q < 4; q++) acc[n][q] = 0.f;
    float sqA = 0.f, sqB = 0.f;
    float pq[3] = {0.f, 0.f, 0.f};

    const int Rg    = (warp & 3) * 16 + g;     // A rows Rg, Rg+8
    const int nhalf = warp >> 2;
    const bool doX2 = (nhalf == 0);
    const bool doP2 = ((warp & 3) == 0);

    for (int s = 0; s < 32; s++) {
        cpa_wait1();
        __syncthreads();
        if (s + 2 < 32) { const int b2 = (s + 2) % 3; ISSUE_STAGE(s + 2, b2); }
        cpa_commit();

        const uint32_t* xb = &pipe[s % 3][0];
        const uint32_t* pb = xb + XWORDS;
#pragma unroll
        for (int kc = 0; kc < 32; kc += 8) {
            const uint32_t a0 = xb[(Rg    ) * 36 + kc + t4];
            const uint32_t a1 = xb[(Rg + 8) * 36 + kc + t4];
            const uint32_t a2 = xb[(Rg    ) * 36 + kc + t4 + 4];
            const uint32_t a3 = xb[(Rg + 8) * 36 + kc + t4 + 4];
            if (doX2) {
                const float f0 = __uint_as_float(a0), f1 = __uint_as_float(a1);
                const float f2 = __uint_as_float(a2), f3 = __uint_as_float(a3);
                sqA = fmaf(f0, f0, sqA); sqA = fmaf(f2, f2, sqA);
                sqB = fmaf(f1, f1, sqB); sqB = fmaf(f3, f3, sqB);
            }
#pragma unroll
            for (int nt = 0; nt < 3; nt++) {
                const int prow = (nhalf * 3 + nt) * 8 + g;
                const uint32_t b0 = pb[prow * 36 + kc + t4];
                const uint32_t b1 = pb[prow * 36 + kc + t4 + 4];
                if (doP2) {
                    const float h0 = __uint_as_float(b0), h1 = __uint_as_float(b1);
                    pq[nt] = fmaf(h0, h0, pq[nt]);
                    pq[nt] = fmaf(h1, h1, pq[nt]);
                }
                asm volatile(
                    "mma.sync.aligned.m16n8k8.row.col.f32.tf32.tf32.f32 "
                    "{%0,%1,%2,%3}, {%4,%5,%6,%7}, {%8,%9}, {%0,%1,%2,%3};"
                    : "+f"(acc[nt][0]), "+f"(acc[nt][1]),
                      "+f"(acc[nt][2]), "+f"(acc[nt][3])
                    : "r"(a0), "r"(a1), "r"(a2), "r"(a3), "r"(b0), "r"(b1));
            }
        }
    }
    __syncthreads();   // all mma done; safe to alias pipe as epilogue scratch

    // aliased epilogue scratch in pipe[0]
    float* ext     = (float*)&pipe[0][0];
    float* x2s     = ext;          // 64
    float* p2s     = ext + 64;     // 48
    float* logit_s = ext + 112;    // 128
    float* simPart = ext + 240;    // 48
    float* wks     = ext + 288;    // 96
    for (int i = tid; i < 384; i += 256)
        ext[i] = (i < 288) ? 0.f : llw[i - 288];
    __syncthreads();

    // quad-reduce squared norms (lanes t4=0..3 share a row)
    sqA += __shfl_xor_sync(0xffffffffu, sqA, 1);
    sqA += __shfl_xor_sync(0xffffffffu, sqA, 2);
    sqB += __shfl_xor_sync(0xffffffffu, sqB, 1);
    sqB += __shfl_xor_sync(0xffffffffu, sqB, 2);
    if (doX2 && t4 == 0) {
        atomicAdd(&x2s[Rg],     sqA);
        atomicAdd(&x2s[Rg + 8], sqB);
    }
#pragma unroll
    for (int nt = 0; nt < 3; nt++) {
        pq[nt] += __shfl_xor_sync(0xffffffffu, pq[nt], 1);
        pq[nt] += __shfl_xor_sync(0xffffffffu, pq[nt], 2);
    }
    if (doP2 && t4 == 0) {
#pragma unroll
        for (int nt = 0; nt < 3; nt++)
            atomicAdd(&p2s[(nhalf * 3 + nt) * 8 + g], pq[nt]);
    }
    __syncthreads();

    const int ra = Rg, rb = Rg + 8;
    const float x2a = x2s[ra], x2b = x2s[rb];
    float lgA0 = 0.f, lgA1 = 0.f, lgB0 = 0.f, lgB1 = 0.f;
    float* dd = out + DIST_OFF + (size_t)row0 * 48;
#pragma unroll
    for (int nt = 0; nt < 3; nt++) {
        const int c0 = (nhalf * 3 + nt) * 8 + t4 * 2, c1 = c0 + 1;
        const float dA0 = fmaf(-2.f, acc[nt][0], x2a + p2s[c0]);
        const float dA1 = fmaf(-2.f, acc[nt][1], x2a + p2s[c1]);
        const float dB0 = fmaf(-2.f, acc[nt][2], x2b + p2s[c0]);
        const float dB1 = fmaf(-2.f, acc[nt][3], x2b + p2s[c1]);
        __stcs((float2*)(dd + (size_t)ra * 48 + c0), make_float2(dA0, dA1));
        __stcs((float2*)(dd + (size_t)rb * 48 + c0), make_float2(dB0, dB1));
        const float sA0 = logf((dA0 + 1.f) / (dA0 + EPSf));
        const float sA1 = logf((dA1 + 1.f) / (dA1 + EPSf));
        const float sB0 = logf((dB0 + 1.f) / (dB0 + EPSf));
        const float sB1 = logf((dB1 + 1.f) / (dB1 + EPSf));
        lgA0 = fmaf(sA0, wks[c0], lgA0); lgA0 = fmaf(sA1, wks[c1], lgA0);
        lgA1 = fmaf(sA0, wks[48 + c0], lgA1); lgA1 = fmaf(sA1, wks[48 + c1], lgA1);
        lgB0 = fmaf(sB0, wks[c0], lgB0); lgB0 = fmaf(sB1, wks[c1], lgB0);
        lgB1 = fmaf(sB0, wks[48 + c0], lgB1); lgB1 = fmaf(sB1, wks[48 + c1], lgB1);
        atomicAdd(&simPart[c0], sA0 + sB0);
        atomicAdd(&simPart[c1], sA1 + sB1);
    }
    atomicAdd(&logit_s[ra * 2 + 0], lgA0);
    atomicAdd(&logit_s[ra * 2 + 1], lgA1);
    atomicAdd(&logit_s[rb * 2 + 0], lgB0);
    atomicAdd(&logit_s[rb * 2 + 1], lgB1);
    __syncthreads();

    if (tid < 128) out[LOGITS_OFF + (size_t)row0 * 2 + tid] = logit_s[tid];
    if (tid < 48)  atomicAdd(&G_SIMSUM[tid], simPart[tid]);
#undef ISSUE_STAGE
}

// ---------------------------------------------------------------------------
// K3: in-block argmax -> u[jstar] to smem -> fused shared copy-out + pos dot.
// ---------------------------------------------------------------------------
__global__ __launch_bounds__(512) void k3_pos(
    const float* __restrict__ shr, const float* __restrict__ bb,
    const int* __restrict__ flag, float* __restrict__ out) {
    __shared__ float us[Hd];
    __shared__ int   js_s;
    const int tid = threadIdx.x;

    if (tid < 32) {
        const int idx = (flag[0] != 0) ? 1 : 0;
        float v = (tid < PPCc) ? G_SIMSUM[idx * PPCc + tid] : -INFINITY;
        int bj = tid;
        for (int o = 16; o; o >>= 1) {
            const float ov = __shfl_xor_sync(0xffffffffu, v, o);
            const int   oj = __shfl_xor_sync(0xffffffffu, bj, o);
            if (ov > v || (ov == v && oj < bj)) { v = ov; bj = oj; }
        }
        if (tid == 0) js_s = idx * PPCc + bj;
    }
    __syncthreads();
    const int js = js_s;
    for (int i = tid; i < Hd; i += 512) us[i] = G_UALL[js * Hd + i];
    __syncthreads();

    const int warp = tid >> 5, lane = tid & 31;
    const int r = blockIdx.x * 16 + warp;
    const float4* src = (const float4*)(shr + (size_t)r * Hd);
    float4*       dst = (float4*)(out + SHARED_OFF + (size_t)r * Hd);
    const float4* uf  = (const float4*)us;
    float a0 = 0.f, a1 = 0.f, a2 = 0.f, a3 = 0.f;
#pragma unroll
    for (int t = lane; t < Hd / 4; t += 32) {
        const float4 v = __ldcs(src + t);
        __stcs(dst + t, v);
        const float4 u4 = uf[t];
        a0 = fmaf(v.x, u4.x, a0);
        a1 = fmaf(v.y, u4.y, a1);
        a2 = fmaf(v.z, u4.z, a2);
        a3 = fmaf(v.w, u4.w, a3);
    }
    float acc = (a0 + a1) + (a2 + a3);
    for (int o = 16; o; o >>= 1) acc += __shfl_xor_sync(0xffffffffu, acc, o);
    if (lane == 0) out[POS_OFF + r] = acc + __ldg(bb);
}

// ---------------------------------------------------------------------------
extern "C" void kernel_launch(void* const* d_in, const int* in_sizes, int n_in,
                              void* d_out, int out_size) {
    const float* x      = (const float*)d_in[0];  // specific_user [B,H]
    const float* shr    = (const float*)d_in[1];  // shared_user   [B,H]
    const float* protos = (const float*)d_in[2];  // [P,H]
    const float* llw    = (const float*)d_in[3];  // [C,P]
    const float* W      = (const float*)d_in[4];  // [1,H,H]
    const float* bb     = (const float*)d_in[5];  // [1]
    const int*   flag   = (const int*)d_in[6];    // scalar
    float* out = (float*)d_out;

    // single memset node (uall + simSum live in one symbol)
    void* scr_ptr = nullptr;
    cudaGetSymbolAddress(&scr_ptr, g_scratch);
    cudaMemsetAsync(scr_ptr, 0, (size_t)(Pp * Hd + Pp) * sizeof(float));

    k2_fused<<<DIST_BLOCKS + UALL_BLOCKS, 256>>>(x, protos, llw, W, out);
    k3_pos  <<<Bsz / 16, 512>>>(shr, bb, flag, out);
}